// round 4
// baseline (speedup 1.0000x reference)
#include <cuda_runtime.h>

#define HH 256
#define WW 256
#define PP (HH * WW)
#define NF 13776
#define NV 6890
#define BATCH 2
#define BIGF 1000000000.0f
#define EPSF 1e-8f
#define TILE 8
#define TGRID 32                 // 32x32 tiles
#define NTILES (TGRID * TGRID)
#define MASKW 432                // ceil(NF/32) = 431, padded
#define NSLICE 8

__device__ float4 g_fa[BATCH * NF];       // A0*inv, B0*inv, A1*inv, B1*inv
__device__ float4 g_fb[BATCH * NF];       // -x2, -y2, z0, z1
__device__ float2 g_fc[BATCH * NF];       // z2, face_index (int bits)
__device__ float4 g_bb[BATCH * NF];       // xmin, xmax, ymin, ymax
__device__ float2 g_sf[BATCH * NF * 3];   // src flow per corner
__device__ unsigned long long g_zb[BATCH * PP];
__device__ unsigned g_mask[BATCH * NTILES * MASKW];
__device__ int g_list[BATCH * NTILES * NF / 8];  // cap NF/8=1722 would overflow; use full below
// NOTE: need guaranteed-safe capacity; use NF (impossible to overflow)
__device__ int g_listfull[(size_t)BATCH * NTILES * NF];
__device__ int g_cnt[BATCH * NTILES];

#define MUL_F32X2(out, a, b) asm("mul.rn.f32x2 %0, %1, %2;" : "=l"(out) : "l"(a), "l"(b))
#define ADD_F32X2(out, a, b) asm("add.rn.f32x2 %0, %1, %2;" : "=l"(out) : "l"(a), "l"(b))
#define FMA_F32X2(out, a, b, c) asm("fma.rn.f32x2 %0, %1, %2, %3;" : "=l"(out) : "l"(a), "l"(b), "l"(c))
#define PACK_F32X2(out, lo, hi) asm("mov.b64 %0, {%1, %2};" : "=l"(out) : "f"(lo), "f"(hi))

__device__ __forceinline__ unsigned int f2sortable(float d) {
    unsigned int u = __float_as_uint(d);
    return u ^ (((unsigned int)((int)u >> 31)) | 0x80000000u);
}

__global__ void setup_kernel(const float* __restrict__ src_cam,
                             const float* __restrict__ src_verts,
                             const float* __restrict__ tgt_cam,
                             const float* __restrict__ tgt_verts,
                             const int*   __restrict__ faces)
{
    int idx = blockIdx.x * blockDim.x + threadIdx.x;
    if (idx >= BATCH * NF) return;
    int b = idx / NF;
    int f = idx - b * NF;

    int i0 = faces[f * 3 + 0];
    int i1 = faces[f * 3 + 1];
    int i2 = faces[f * 3 + 2];

    float tc0 = tgt_cam[b * 3 + 0];
    float tc1 = tgt_cam[b * 3 + 1];
    float tc2 = tgt_cam[b * 3 + 2];
    const float* tv = tgt_verts + (size_t)b * NV * 3;

    float x0 = tc0 * (tv[i0 * 3 + 0] + tc1);
    float y0 = -(tc0 * (tv[i0 * 3 + 1] + tc2));
    float z0 = tv[i0 * 3 + 2];
    float x1 = tc0 * (tv[i1 * 3 + 0] + tc1);
    float y1 = -(tc0 * (tv[i1 * 3 + 1] + tc2));
    float z1 = tv[i1 * 3 + 2];
    float x2 = tc0 * (tv[i2 * 3 + 0] + tc1);
    float y2 = -(tc0 * (tv[i2 * 3 + 1] + tc2));
    float z2 = tv[i2 * 3 + 2];

    float denom = (y1 - y2) * (x0 - x2) + (x2 - x1) * (y0 - y2);
    bool valid = fabsf(denom) >= EPSF;
    float inv = 1.0f / (valid ? denom : 1.0f);

    g_fa[idx] = make_float4((y1 - y2) * inv, (x2 - x1) * inv,
                            (y2 - y0) * inv, (x0 - x2) * inv);
    g_fb[idx] = make_float4(-x2, -y2, z0, z1);
    g_fc[idx] = make_float2(z2, __int_as_float(f));

    const float pad = 2.0f / 256.0f;
    float xmn = fminf(x0, fminf(x1, x2)) - pad;
    float xmx = fmaxf(x0, fmaxf(x1, x2)) + pad;
    float ymn = fminf(y0, fminf(y1, y2)) - pad;
    float ymx = fmaxf(y0, fmaxf(y1, y2)) + pad;
    if (!valid) { xmn = 1e30f; xmx = -1e30f; ymn = 1e30f; ymx = -1e30f; }
    g_bb[idx] = make_float4(xmn, xmx, ymn, ymx);

    float sc0 = src_cam[b * 3 + 0];
    float sc1 = src_cam[b * 3 + 1];
    float sc2 = src_cam[b * 3 + 2];
    const float* sv = src_verts + (size_t)b * NV * 3;
    g_sf[idx * 3 + 0] = make_float2(sc0 * (sv[i0 * 3 + 0] + sc1), sc0 * (sv[i0 * 3 + 1] + sc2));
    g_sf[idx * 3 + 1] = make_float2(sc0 * (sv[i1 * 3 + 0] + sc1), sc0 * (sv[i1 * 3 + 1] + sc2));
    g_sf[idx * 3 + 2] = make_float2(sc0 * (sv[i2 * 3 + 0] + sc1), sc0 * (sv[i2 * 3 + 1] + sc2));
}

__global__ void zinit_kernel()
{
    int i = blockIdx.x * blockDim.x + threadIdx.x;
    if (i < BATCH * NTILES * MASKW) g_mask[i] = 0u;
    if (i < BATCH * PP) {
        g_zb[i] = ((unsigned long long)f2sortable(BIGF) << 32) | 0xFFFFFFFFull;
    }
    if (i < BATCH * NTILES) g_cnt[i] = 0;
}

// face-parallel binning: set bit (tile, face) for every tile the face may touch
__global__ void bin_kernel()
{
    int idx = blockIdx.x * blockDim.x + threadIdx.x;
    if (idx >= BATCH * NF) return;
    int b = idx / NF;
    int f = idx - b * NF;

    float4 bx = g_bb[idx];
    if (bx.x > bx.y) return;  // degenerate

    int tx0 = min(max((int)floorf(((bx.x + 1.0f) * 128.0f - 7.5f) * 0.125f), 0), TGRID - 1);
    int tx1 = min(max((int)floorf(((bx.y + 1.0f) * 128.0f - 0.5f) * 0.125f), 0), TGRID - 1);
    int ty0 = min(max((int)floorf(((bx.z + 1.0f) * 128.0f - 7.5f) * 0.125f), 0), TGRID - 1);
    int ty1 = min(max((int)floorf(((bx.w + 1.0f) * 128.0f - 0.5f) * 0.125f), 0), TGRID - 1);
    if (bx.x > 1.0f || bx.y < -1.0f || bx.z > 1.0f || bx.w < -1.0f) return;

    float4 a  = g_fa[idx];
    float4 c4 = g_fb[idx];   // -x2, -y2
    const float hx = 3.5f / 128.0f;
    const float hy = 3.5f / 128.0f;
    float sh0 = fabsf(a.x) * hx + fabsf(a.y) * hy;
    float sh1 = fabsf(a.z) * hx + fabsf(a.w) * hy;
    float sh2 = fabsf(a.x + a.z) * hx + fabsf(a.y + a.w) * hy;

    unsigned* mk = g_mask + (size_t)(b * NTILES) * MASKW;
    int word = f >> 5;
    unsigned bit = 1u << (f & 31);

    for (int ty = ty0; ty <= ty1; ty++) {
        float cy = ((float)(8 * ty) + 4.0f) / 128.0f - 1.0f;
        float dyc = cy + c4.y;
        for (int tx = tx0; tx <= tx1; tx++) {
            float cx = ((float)(8 * tx) + 4.0f) / 128.0f - 1.0f;
            float dxc = cx + c4.x;
            float w0c = a.x * dxc + a.y * dyc;
            float w1c = a.z * dxc + a.w * dyc;
            float w2c = 1.0f - w0c - w1c;
            float m0 = 1e-5f * (fabsf(w0c) + sh0) + 1e-6f;
            float m1 = 1e-5f * (fabsf(w1c) + sh1) + 1e-6f;
            float m2 = 1e-5f * (fabsf(w2c) + sh2) + 1e-6f;
            if ((w0c + sh0 >= -m0) & (w1c + sh1 >= -m1) & (w2c + sh2 >= -m2)) {
                atomicOr(&mk[(ty * TGRID + tx) * MASKW + word], bit);
            }
        }
    }
}

// one warp per tile: bitmask -> ascending face list (deterministic)
__global__ __launch_bounds__(256) void compact_kernel()
{
    int warp = (blockIdx.x * 256 + threadIdx.x) >> 5;
    int lane = threadIdx.x & 31;
    if (warp >= BATCH * NTILES) return;

    const unsigned* mk = g_mask + (size_t)warp * MASKW;
    int* lst = g_listfull + (size_t)warp * NF;

    int off = 0;
    for (int w0 = 0; w0 < MASKW; w0 += 32) {
        int wi = w0 + lane;
        unsigned wd = (wi < MASKW) ? mk[wi] : 0u;
        int pc = __popc(wd);
        int sc = pc;
        #pragma unroll
        for (int d = 1; d < 32; d <<= 1) {
            int n = __shfl_up_sync(0xffffffffu, sc, d);
            if (lane >= d) sc += n;
        }
        int excl = sc - pc;
        int fbase = wi << 5;
        unsigned m = wd;
        int j = 0;
        while (m) {
            int bpos = __ffs(m) - 1;
            m &= m - 1;
            lst[off + excl + j] = fbase + bpos;
            j++;
        }
        off += __shfl_sync(0xffffffffu, sc, 31);
    }
    if (lane == 0) g_cnt[warp] = off;
}

__global__ __launch_bounds__(32) void raster_kernel()
{
    __shared__ float4 sA[32];  // (ax,ax,ay,ay)
    __shared__ float4 sB[32];  // (az,az,aw,aw)
    __shared__ float4 sC[32];  // (nx2,nx2,ny2,ny2)
    __shared__ float4 sD[32];  // (z0,z0,z1,z1)
    __shared__ float4 sE[32];  // (z2,z2,fid,fid)

    const int b     = blockIdx.z;
    const int slice = blockIdx.y;
    const int tile  = blockIdx.x;
    const int tx    = tile & (TGRID - 1);
    const int ty    = tile >> 5;
    const int lane  = threadIdx.x;

    const int len = g_cnt[b * NTILES + tile];
    const int start = (len * slice) / NSLICE;
    const int end   = (len * (slice + 1)) / NSLICE;
    if (start >= end) return;

    const int* lst = g_listfull + (size_t)(b * NTILES + tile) * NF;
    const float4* __restrict__ fa = g_fa + b * NF;
    const float4* __restrict__ fb = g_fb + b * NF;
    const float2* __restrict__ fc = g_fc + b * NF;

    const int p0    = lane * 2;
    const int px0_i = tx * TILE + (p0 & 7);
    const int py_i  = ty * TILE + (p0 >> 3);
    const float px0 = ((float)px0_i + 0.5f) / 256.0f * 2.0f - 1.0f;
    const float px1 = ((float)(px0_i + 1) + 0.5f) / 256.0f * 2.0f - 1.0f;
    const float py  = ((float)py_i + 0.5f) / 256.0f * 2.0f - 1.0f;

    unsigned long long pxp, pyp;
    PACK_F32X2(pxp, px0, px1);
    PACK_F32X2(pyp, py, py);
    const unsigned long long onesp    = 0x3f8000003f800000ull;
    const unsigned long long negonesp = 0xbf800000bf800000ull;

    float zmin0 = BIGF, zmin1 = BIGF;
    int   best0 = -1,   best1 = -1;

    for (int base = start; base < end; base += 32) {
        int e = base + lane;
        if (e < end) {
            int f = lst[e];
            float4 a  = fa[f];
            float4 c4 = fb[f];
            float2 e2 = fc[f];
            sA[lane] = make_float4(a.x, a.x, a.y, a.y);
            sB[lane] = make_float4(a.z, a.z, a.w, a.w);
            sC[lane] = make_float4(c4.x, c4.x, c4.y, c4.y);
            sD[lane] = make_float4(c4.z, c4.z, c4.w, c4.w);
            sE[lane] = make_float4(e2.x, e2.x, e2.y, e2.y);
        }
        __syncwarp();
        int cnt2 = min(32, end - base);

        const ulonglong2* qA = (const ulonglong2*)sA;
        const ulonglong2* qB = (const ulonglong2*)sB;
        const ulonglong2* qC = (const ulonglong2*)sC;
        const ulonglong2* qD = (const ulonglong2*)sD;
        const ulonglong2* qE = (const ulonglong2*)sE;

        for (int k = 0; k < cnt2; k++) {
            ulonglong2 a01 = qA[k];
            ulonglong2 a23 = qB[k];
            ulonglong2 cxy = qC[k];
            ulonglong2 z01 = qD[k];
            ulonglong2 z2f = qE[k];

            unsigned long long dxp, dyp, t0, t1, w0, w1, tmp, w2, d;
            ADD_F32X2(dxp, pxp, cxy.x);
            ADD_F32X2(dyp, pyp, cxy.y);
            MUL_F32X2(t0, a01.y, dyp);
            FMA_F32X2(w0, a01.x, dxp, t0);
            MUL_F32X2(t1, a23.y, dyp);
            FMA_F32X2(w1, a23.x, dxp, t1);
            FMA_F32X2(tmp, w0, negonesp, onesp);   // 1 - w0
            FMA_F32X2(w2,  w1, negonesp, tmp);     // (1-w0) - w1
            MUL_F32X2(d, w2, z2f.x);
            FMA_F32X2(d, w1, z01.y, d);
            FMA_F32X2(d, w0, z01.x, d);

            unsigned long long orb = w0 | w1 | w2;
            int o_lo = (int)(unsigned)orb;
            int o_hi = (int)(unsigned)(orb >> 32);
            float d0 = __uint_as_float((unsigned)d);
            float d1 = __uint_as_float((unsigned)(d >> 32));
            int fid = (int)(unsigned)z2f.y;  // int bits in lo half

            if ((o_lo >= 0) && (d0 < zmin0)) { zmin0 = d0; best0 = __float_as_int(__uint_as_float((unsigned)fid)); best0 = fid; }
            if ((o_hi >= 0) && (d1 < zmin1)) { zmin1 = d1; best1 = fid; }
        }
        __syncwarp();
    }

    unsigned long long* zb = g_zb + (size_t)b * PP;
    if (best0 >= 0) {
        unsigned long long key =
            ((unsigned long long)f2sortable(zmin0) << 32) | (unsigned int)best0;
        atomicMin(&zb[py_i * WW + px0_i], key);
    }
    if (best1 >= 0) {
        unsigned long long key =
            ((unsigned long long)f2sortable(zmin1) << 32) | (unsigned int)(best1);
        atomicMin(&zb[py_i * WW + px0_i + 1], key);
    }
}

__global__ __launch_bounds__(256) void resolve_kernel(const float* __restrict__ src_img,
                                                      float* __restrict__ out)
{
    const int b   = blockIdx.y;
    const int pix = blockIdx.x * 256 + threadIdx.x;
    const int px_i = pix & (WW - 1);
    const int py_i = pix >> 8;
    const float px = ((float)px_i + 0.5f) / 256.0f * 2.0f - 1.0f;
    const float py = ((float)py_i + 0.5f) / 256.0f * 2.0f - 1.0f;

    unsigned long long key = g_zb[(size_t)b * PP + pix];
    unsigned int face = (unsigned int)(key & 0xFFFFFFFFull);

    float fx, fy;
    if (face != 0xFFFFFFFFu) {
        int gi = b * NF + (int)face;
        float4 a  = g_fa[gi];
        float4 c4 = g_fb[gi];   // -x2, -y2
        float dx = px + c4.x;
        float dy = py + c4.y;
        float w0 = fmaf(a.x, dx, a.y * dy);
        float w1 = fmaf(a.z, dx, a.w * dy);
        float w2 = 1.0f - w0 - w1;
        float2 s0 = g_sf[gi * 3 + 0];
        float2 s1 = g_sf[gi * 3 + 1];
        float2 s2 = g_sf[gi * 3 + 2];
        fx = w0 * s0.x + w1 * s1.x + w2 * s2.x;
        fy = w0 * s0.y + w1 * s1.y + w2 * s2.y;
    } else {
        fx = -2.0f;
        fy = -2.0f;
    }

    float ix = fminf(fmaxf(((fx + 1.0f) * 256.0f - 1.0f) * 0.5f, 0.0f), 255.0f);
    float iy = fminf(fmaxf(((fy + 1.0f) * 256.0f - 1.0f) * 0.5f, 0.0f), 255.0f);
    float x0f = floorf(ix);
    float y0f = floorf(iy);
    float wx = ix - x0f;
    float wy = iy - y0f;
    int x0i = (int)x0f;
    int y0i = (int)y0f;
    int x1i = min(x0i + 1, WW - 1);
    int y1i = min(y0i + 1, HH - 1);

    float wa = (1.0f - wx) * (1.0f - wy);
    float wb = wx * (1.0f - wy);
    float wc = (1.0f - wx) * wy;
    float wd = wx * wy;

    const float* img = src_img + (size_t)b * 3 * HH * WW;
    #pragma unroll
    for (int c = 0; c < 3; c++) {
        const float* p = img + (size_t)c * HH * WW;
        float Ia = p[y0i * WW + x0i];
        float Ib = p[y0i * WW + x1i];
        float Ic = p[y1i * WW + x0i];
        float Id = p[y1i * WW + x1i];
        out[(((size_t)b * 3 + c) * HH + py_i) * WW + px_i] =
            Ia * wa + Ib * wb + Ic * wc + Id * wd;
    }
}

extern "C" void kernel_launch(void* const* d_in, const int* in_sizes, int n_in,
                              void* d_out, int out_size)
{
    const float* src_img   = (const float*)d_in[0];
    const float* src_cam   = (const float*)d_in[1];
    const float* src_verts = (const float*)d_in[2];
    const float* tgt_cam   = (const float*)d_in[3];
    const float* tgt_verts = (const float*)d_in[4];
    const int*   faces     = (const int*)d_in[5];
    float* out = (float*)d_out;

    int n = BATCH * NF;
    setup_kernel<<<(n + 255) / 256, 256>>>(src_cam, src_verts, tgt_cam, tgt_verts, faces);
    zinit_kernel<<<(BATCH * NTILES * MASKW + 255) / 256, 256>>>();
    bin_kernel<<<(n + 255) / 256, 256>>>();
    compact_kernel<<<(BATCH * NTILES * 32 + 255) / 256, 256>>>();
    dim3 rgrid(NTILES, NSLICE, BATCH);
    raster_kernel<<<rgrid, 32>>>();
    dim3 ggrid(PP / 256, BATCH);
    resolve_kernel<<<ggrid, 256>>>(src_img, out);
}